// round 2
// baseline (speedup 1.0000x reference)
#include <cuda_runtime.h>

#define Dd   32
#define Nn   256
#define Bb   4
#define Hh   512
#define Kk   256          // H/2
#define TMP_PITCH 33
#define ZJ_PITCH  33

// dynamic smem layout:
//   tmpS : 512*33 floats  (tmp[h][c], padded)
//   zjS  : 256*33 floats  (z[b][j][c], padded)
//   h1S  : 32*512 floats  (h1 tile [j_local][h])
#define SMEM_BYTES ((Hh*TMP_PITCH + Nn*ZJ_PITCH + 32*Hh) * 4)

extern __shared__ float smem[];

__global__ __launch_bounds__(256, 1)
void decoder_fused_kernel(const float* __restrict__ z,
                          const float* __restrict__ motif_mask,
                          const float* __restrict__ W1,
                          const float* __restrict__ b1,
                          const float* __restrict__ W2,
                          const float* __restrict__ b2,
                          const float* __restrict__ W3,
                          const float* __restrict__ b3,
                          float* __restrict__ out)
{
    float* tmpS = smem;                       // 512*33
    float* zjS  = tmpS + Hh * TMP_PITCH;      // 256*33
    float* h1S  = zjS  + Nn * ZJ_PITCH;       // 32*512

    __shared__ float ziS[Dd];
    __shared__ float mmS[Nn];

    const int t  = threadIdx.x;
    const int bi = blockIdx.x;           // b*256 + i
    const int b  = bi >> 8;
    const int i  = bi & 255;

    // ---- stage inputs ----
    if (t < Dd) ziS[t] = z[bi * Dd + t];
    mmS[t] = motif_mask[b * Nn + t];
    for (int idx = t; idx < Nn * Dd; idx += 256) {
        int j = idx >> 5, c = idx & 31;
        zjS[j * ZJ_PITCH + c] = z[(b * Nn + j) * Dd + c];
    }
    __syncthreads();

    // ---- phase 1: tmp[h][c] = sum_a zi[a] * W1[(a*32+c)*512 + h] ----
    // lanes take consecutive h -> coalesced W1 reads.
    for (int r = 0; r < (Hh * Dd) / 256; r++) {
        int idx = t + 256 * r;
        int c = idx >> 9;        // 0..31
        int h = idx & 511;       // 0..511
        float acc = 0.f;
        const float* w1p = W1 + (size_t)c * Hh + h;   // + a*32*512 per step
        #pragma unroll 8
        for (int a = 0; a < Dd; a++)
            acc += ziS[a] * w1p[(size_t)a * Dd * Hh];
        tmpS[h * TMP_PITCH + c] = acc;
    }
    __syncthreads();

    const int warp = t >> 5;     // 0..7
    const int lane = t & 31;
    const float mi = mmS[i];
    const float b3v = b3[0];

    // preload per-thread b2 / W3 (k = lane*8 + e)
    float b2r[8], w3r[8];
    #pragma unroll
    for (int e = 0; e < 8; e++) {
        b2r[e] = b2[lane * 8 + e];
        w3r[e] = W3[lane * 8 + e];
    }

    const float4* W2v = (const float4*)W2;   // W2[h*256 + k] -> float4 idx h*64 + lane*2

    for (int jt0 = 0; jt0 < Nn; jt0 += 32) {
        // ---- h1 tile: j_local = warp*4 + q, h = lane + 32*p ----
        {
            float acc[4][16];
            #pragma unroll
            for (int q = 0; q < 4; q++)
                #pragma unroll
                for (int p = 0; p < 16; p++) acc[q][p] = 0.f;

            #pragma unroll 4
            for (int c = 0; c < Dd; c++) {
                float zq[4];
                #pragma unroll
                for (int q = 0; q < 4; q++)
                    zq[q] = zjS[(jt0 + warp * 4 + q) * ZJ_PITCH + c];   // broadcast
                #pragma unroll
                for (int p = 0; p < 16; p++) {
                    float tv = tmpS[(lane + 32 * p) * TMP_PITCH + c];   // conflict-free
                    #pragma unroll
                    for (int q = 0; q < 4; q++)
                        acc[q][p] += zq[q] * tv;
                }
            }
            #pragma unroll
            for (int q = 0; q < 4; q++)
                #pragma unroll
                for (int p = 0; p < 16; p++) {
                    int h = lane + 32 * p;
                    float v = acc[q][p] + b1[h];
                    h1S[(warp * 4 + q) * Hh + h] = fmaxf(v, 0.f);
                }
        }
        __syncthreads();

        // ---- h2: acc2[q][e] = sum_h h1[j][h] * W2[h][lane*8+e] ----
        float acc2[4][8];
        #pragma unroll
        for (int q = 0; q < 4; q++)
            #pragma unroll
            for (int e = 0; e < 8; e++) acc2[q][e] = 0.f;

        #pragma unroll 2
        for (int h = 0; h < Hh; h++) {
            float a4[4];
            #pragma unroll
            for (int q = 0; q < 4; q++)
                a4[q] = h1S[(warp * 4 + q) * Hh + h];                  // broadcast
            float4 w0 = W2v[h * 64 + lane * 2];
            float4 w1 = W2v[h * 64 + lane * 2 + 1];
            #pragma unroll
            for (int q = 0; q < 4; q++) {
                acc2[q][0] += a4[q] * w0.x;  acc2[q][1] += a4[q] * w0.y;
                acc2[q][2] += a4[q] * w0.z;  acc2[q][3] += a4[q] * w0.w;
                acc2[q][4] += a4[q] * w1.x;  acc2[q][5] += a4[q] * w1.y;
                acc2[q][6] += a4[q] * w1.z;  acc2[q][7] += a4[q] * w1.w;
            }
        }

        // ---- relu + b2, dot W3, warp reduction over k ----
        float part[4];
        #pragma unroll
        for (int q = 0; q < 4; q++) {
            float s = 0.f;
            #pragma unroll
            for (int e = 0; e < 8; e++) {
                float v = fmaxf(acc2[q][e] + b2r[e], 0.f);
                s += v * w3r[e];
            }
            part[q] = s;
        }
        #pragma unroll
        for (int off = 16; off > 0; off >>= 1)
            #pragma unroll
            for (int q = 0; q < 4; q++)
                part[q] += __shfl_down_sync(0xffffffffu, part[q], off);

        if (lane == 0) {
            #pragma unroll
            for (int q = 0; q < 4; q++) {
                int j = jt0 + warp * 4 + q;
                float lg = (part[q] + b3v) * mi * mmS[j];
                size_t o = ((size_t)bi) * Nn + j;
                // out = [contact_map | contact_logits]
                out[o] = 1.f / (1.f + __expf(-lg));
                out[(size_t)Bb * Nn * Nn + o] = lg;
            }
        }
        __syncthreads();   // protect h1S before next tile overwrites it
    }
}

extern "C" void kernel_launch(void* const* d_in, const int* in_sizes, int n_in,
                              void* d_out, int out_size)
{
    const float* z   = (const float*)d_in[0];
    const float* mm  = (const float*)d_in[1];
    // d_in[2] = residue_mask (unused by reference)
    const float* W1  = (const float*)d_in[3];
    const float* b1  = (const float*)d_in[4];
    const float* W2  = (const float*)d_in[5];
    const float* b2  = (const float*)d_in[6];
    const float* W3  = (const float*)d_in[7];
    const float* b3  = (const float*)d_in[8];
    float* out = (float*)d_out;

    cudaFuncSetAttribute(decoder_fused_kernel,
                         cudaFuncAttributeMaxDynamicSharedMemorySize, SMEM_BYTES);

    decoder_fused_kernel<<<Bb * Nn, 256, SMEM_BYTES>>>(
        z, mm, W1, b1, W2, b2, W3, b3, out);
}

// round 4
// speedup vs baseline: 10.5931x; 10.5931x over previous
#include <cuda_runtime.h>
#include <cuda_fp16.h>
#include <stdint.h>

#define Bb 4
#define Nn 256
#define Dd 32
#define Hh 512
#define Kk 256

// device scratch
__device__ uint4 g_tmph[((size_t)Bb*Nn*Hh*Dd*2)/16];   // 33.5 MB fp16 TMP [bi][h][c]
__device__ uint4 g_w2t [(8*Kk*128)/16];                 // 256 KB fp16 W2^T chunks, XOR-swizzled

// ---------------- helpers ----------------
__device__ __forceinline__ uint32_t s2u(const void* p) {
    uint32_t a;
    asm("{ .reg .u64 t; cvta.to.shared.u64 t, %1; cvt.u32.u64 %0, t; }" : "=r"(a) : "l"(p));
    return a;
}
__device__ __forceinline__ void mbar_init(uint32_t m, uint32_t c) {
    asm volatile("mbarrier.init.shared.b64 [%0], %1;" :: "r"(m), "r"(c) : "memory");
}
__device__ __forceinline__ void mbar_expect(uint32_t m, uint32_t bytes) {
    asm volatile("mbarrier.arrive.expect_tx.shared.b64 _, [%0], %1;" :: "r"(m), "r"(bytes) : "memory");
}
__device__ __forceinline__ void mbar_wait(uint32_t m, uint32_t ph) {
    asm volatile(
        "{\n\t.reg .pred P;\n\t"
        "LW%=:\n\t"
        "mbarrier.try_wait.parity.shared.b64 P, [%0], %1, 0x989680;\n\t"
        "@P bra LD%=;\n\t"
        "bra LW%=;\n\t"
        "LD%=:\n\t}"
        :: "r"(m), "r"(ph) : "memory");
}
__device__ __forceinline__ void bulk_g2s(uint32_t dst, const void* src, uint32_t bytes, uint32_t mbar) {
    asm volatile("cp.async.bulk.shared::cluster.global.mbarrier::complete_tx::bytes [%0], [%1], %2, [%3];"
                 :: "r"(dst), "l"(src), "r"(bytes), "r"(mbar) : "memory");
}
__device__ __forceinline__ void mma16816(float d[4], const uint32_t a[4], const uint32_t b[2]) {
    asm volatile("mma.sync.aligned.m16n8k16.row.col.f32.f16.f16.f32 "
                 "{%0,%1,%2,%3}, {%4,%5,%6,%7}, {%8,%9}, {%0,%1,%2,%3};"
                 : "+f"(d[0]), "+f"(d[1]), "+f"(d[2]), "+f"(d[3])
                 : "r"(a[0]), "r"(a[1]), "r"(a[2]), "r"(a[3]), "r"(b[0]), "r"(b[1]));
}

// ---------------- prep kernels ----------------
// W2T chunk layout: [hc][k=256 rows of 128B][64 h halves], bytes XOR-swizzled by ((k&7)<<4)
__global__ void __launch_bounds__(256) prep_w2t_kernel(const float* __restrict__ W2) {
    int idx = blockIdx.x * 256 + threadIdx.x;      // 8*256*64
    int hc   = idx >> 14;
    int r    = idx & 16383;
    int hcol = r >> 8;
    int k    = r & 255;
    __half v = __float2half(W2[(hc * 64 + hcol) * Kk + k]);
    uint32_t byt = (uint32_t)hc * 32768u + (uint32_t)k * 128u + (((uint32_t)hcol * 2u) ^ (((uint32_t)k & 7u) << 4));
    *(__half*)((char*)g_w2t + byt) = v;
}

// TMP[bi][h][c] = sum_a z[bi][a] * W1[(a*32+c)*512 + h]
__global__ void __launch_bounds__(256) prep_tmp_kernel(const float* __restrict__ z,
                                                       const float* __restrict__ W1) {
    __shared__ float zs[64][33];
    __shared__ float W1s[32][257];
    int it = blockIdx.x;
    int ct = blockIdx.y;
    int t  = threadIdx.x;

    for (int idx = t; idx < 64 * 32; idx += 256) {
        int r = idx >> 5, a = idx & 31;
        zs[r][a] = z[(it * 64 + r) * Dd + a];
    }
    for (int fc = 0; fc < 4; fc++) {
        __syncthreads();
        {
            int fglob = ct * 1024 + fc * 256 + t;
            int c = fglob >> 9, h = fglob & 511;
            #pragma unroll
            for (int a = 0; a < 32; a++)
                W1s[a][t] = W1[(a * Dd + c) * Hh + h];
        }
        __syncthreads();
        int fglob = ct * 1024 + fc * 256 + t;
        int c = fglob >> 9, h = fglob & 511;
        #pragma unroll
        for (int ig = 0; ig < 4; ig++) {
            float acc[16];
            #pragma unroll
            for (int ii = 0; ii < 16; ii++) acc[ii] = 0.f;
            #pragma unroll 8
            for (int a = 0; a < 32; a++) {
                float w = W1s[a][t];
                #pragma unroll
                for (int ii = 0; ii < 16; ii++)
                    acc[ii] += w * zs[ig * 16 + ii][a];
            }
            #pragma unroll
            for (int ii = 0; ii < 16; ii++) {
                size_t bi = (size_t)it * 64 + ig * 16 + ii;
                ((__half*)g_tmph)[bi * 16384 + (size_t)h * 32 + c] = __float2half(acc[ii]);
            }
        }
    }
}

// ---------------- main kernel ----------------
// dyn smem: zjS 256*40*2=20480 @0 | tmpS 512*40*2=40960 @20480 | W2TS 2*32768 @61440 | h1 64*72*2=9216 @126976
#define ZJ_OFF  0
#define TMP_OFF 20480
#define W2_OFF  61440
#define H1_OFF  126976
#define MAIN_SMEM 136192

__global__ void __launch_bounds__(256, 1)
decoder_hmma_kernel(const float* __restrict__ z, const float* __restrict__ mm,
                    const float* __restrict__ b1, const float* __restrict__ b2,
                    const float* __restrict__ W3, const float* __restrict__ b3,
                    float* __restrict__ out)
{
    extern __shared__ char dsm[];
    __shared__ float b1s[512], b2s[256], w3s[256], mmS[256], part[64];
    __shared__ __align__(8) uint64_t mbars[2];

    const int t    = threadIdx.x;
    const int w    = t >> 5;
    const int lane = t & 31;
    const int wr   = w >> 2;    // 0..1  (j 32-row group)
    const int wc   = w & 3;     // 0..3  (k/h col group)
    const int lr   = lane >> 2; // fragment row
    const int lc   = (lane & 3) * 2;

    const int bi = blockIdx.x;
    const int b  = bi >> 8;
    const int i  = bi & 255;

    const uint32_t smb = s2u(dsm);
    const uint32_t mb0 = s2u(mbars);

    // ---- fills ----
    {   // zjS: row j = t, 32 halves padded to 40
        const float4* zp = (const float4*)(z + ((size_t)b * Nn + t) * Dd);
        #pragma unroll
        for (int c4 = 0; c4 < 8; c4++) {
            float4 v = zp[c4];
            __half2* zr = (__half2*)(dsm + ZJ_OFF + t * 80);
            zr[c4 * 2]     = __floats2half2_rn(v.x, v.y);
            zr[c4 * 2 + 1] = __floats2half2_rn(v.z, v.w);
        }
    }
    {   // tmpS: 512 rows x 64B (fp16), padded to 80B rows
        const char* gsrc = (const char*)g_tmph + (size_t)bi * 32768;
        #pragma unroll
        for (int r8 = 0; r8 < 8; r8++) {
            int idx = t + 256 * r8;
            int row = idx >> 2, q = idx & 3;
            uint4 v = *(const uint4*)(gsrc + row * 64 + q * 16);
            *(uint4*)(dsm + TMP_OFF + row * 80 + q * 16) = v;
        }
    }
    for (int k = t; k < 512; k += 256) b1s[k] = b1[k];
    for (int k = t; k < 256; k += 256) { b2s[k] = b2[k]; w3s[k] = W3[k]; mmS[k] = mm[b * Nn + k]; }
    { int k = t + 0;   if (k < 256) {} }
    for (int k = t; k < 256; k += 256) {}  // (no-op)
    if (t == 0) { mbar_init(mb0, 1); mbar_init(mb0 + 8, 1); }
    __syncthreads();
    if (t == 0) {
        mbar_expect(mb0,     32768); bulk_g2s(smb + W2_OFF,          (const char*)g_w2t,          32768, mb0);
        mbar_expect(mb0 + 8, 32768); bulk_g2s(smb + W2_OFF + 32768, (const char*)g_w2t + 32768, 32768, mb0 + 8);
    }

    const float mi  = mmS[i];
    const float b3v = b3[0];
    const char* h1p = dsm + H1_OFF;

    for (int jt = 0; jt < 4; jt++) {
        if (t < 64) part[t] = 0.f;
        float acc2[2][8][4];
        #pragma unroll
        for (int mt = 0; mt < 2; mt++)
            #pragma unroll
            for (int nt = 0; nt < 8; nt++)
                #pragma unroll
                for (int e = 0; e < 4; e++) acc2[mt][nt][e] = 0.f;

        for (int hc = 0; hc < 8; hc++) {
            const int g = jt * 8 + hc;

            // ---- MMA1: h1[64j x 64h] = Zj @ TMP  (K=32) ----
            float acc1[2][2][4];
            #pragma unroll
            for (int mt = 0; mt < 2; mt++)
                #pragma unroll
                for (int nt = 0; nt < 2; nt++)
                    #pragma unroll
                    for (int e = 0; e < 4; e++) acc1[mt][nt][e] = 0.f;

            #pragma unroll
            for (int kk = 0; kk < 2; kk++) {
                const int c = kk * 16 + lc;
                uint32_t bf1[2][2];
                #pragma unroll
                for (int nt = 0; nt < 2; nt++) {
                    int nh = hc * 64 + wc * 16 + nt * 8 + lr;
                    bf1[nt][0] = *(const uint32_t*)(dsm + TMP_OFF + (nh * 40 + c) * 2);
                    bf1[nt][1] = *(const uint32_t*)(dsm + TMP_OFF + (nh * 40 + c + 8) * 2);
                }
                #pragma unroll
                for (int mt = 0; mt < 2; mt++) {
                    int j0 = jt * 64 + wr * 32 + mt * 16 + lr;
                    uint32_t a[4];
                    a[0] = *(const uint32_t*)(dsm + ZJ_OFF + (j0 * 40 + c) * 2);
                    a[1] = *(const uint32_t*)(dsm + ZJ_OFF + ((j0 + 8) * 40 + c) * 2);
                    a[2] = *(const uint32_t*)(dsm + ZJ_OFF + (j0 * 40 + c + 8) * 2);
                    a[3] = *(const uint32_t*)(dsm + ZJ_OFF + ((j0 + 8) * 40 + c + 8) * 2);
                    mma16816(acc1[mt][0], a, bf1[0]);
                    mma16816(acc1[mt][1], a, bf1[1]);
                }
            }
            // bias + relu -> fp16 h1S
            #pragma unroll
            for (int mt = 0; mt < 2; mt++)
                #pragma unroll
                for (int nt = 0; nt < 2; nt++) {
                    int rl = wr * 32 + mt * 16 + lr;
                    int hl = wc * 16 + nt * 8 + lc;
                    int hg = hc * 64 + hl;
                    float v0 = fmaxf(acc1[mt][nt][0] + b1s[hg],     0.f);
                    float v1 = fmaxf(acc1[mt][nt][1] + b1s[hg + 1], 0.f);
                    float v2 = fmaxf(acc1[mt][nt][2] + b1s[hg],     0.f);
                    float v3 = fmaxf(acc1[mt][nt][3] + b1s[hg + 1], 0.f);
                    *(__half2*)(h1p + (rl * 72 + hl) * 2)       = __floats2half2_rn(v0, v1);
                    *(__half2*)(h1p + ((rl + 8) * 72 + hl) * 2) = __floats2half2_rn(v2, v3);
                }

            mbar_wait(mb0 + (g & 1) * 8, (g >> 1) & 1);
            __syncthreads();

            // ---- MMA2: acc2 += h1 @ W2chunk  (K=64) ----
            const char* wbp = dsm + W2_OFF + (g & 1) * 32768;
            #pragma unroll
            for (int kk = 0; kk < 4; kk++) {
                const int hb = kk * 16 + lc;
                uint32_t bf[8][2];
                #pragma unroll
                for (int nt = 0; nt < 8; nt++) {
                    int n = wc * 64 + nt * 8 + lr;
                    uint32_t x0 = ((uint32_t)(hb * 2))       ^ (((uint32_t)n & 7u) << 4);
                    uint32_t x1 = ((uint32_t)((hb + 8) * 2)) ^ (((uint32_t)n & 7u) << 4);
                    bf[nt][0] = *(const uint32_t*)(wbp + n * 128 + x0);
                    bf[nt][1] = *(const uint32_t*)(wbp + n * 128 + x1);
                }
                #pragma unroll
                for (int mt = 0; mt < 2; mt++) {
                    int rl = wr * 32 + mt * 16 + lr;
                    uint32_t a[4];
                    a[0] = *(const uint32_t*)(h1p + (rl * 72 + hb) * 2);
                    a[1] = *(const uint32_t*)(h1p + ((rl + 8) * 72 + hb) * 2);
                    a[2] = *(const uint32_t*)(h1p + (rl * 72 + hb + 8) * 2);
                    a[3] = *(const uint32_t*)(h1p + ((rl + 8) * 72 + hb + 8) * 2);
                    #pragma unroll
                    for (int nt = 0; nt < 8; nt++)
                        mma16816(acc2[mt][nt], a, bf[nt]);
                }
            }
            __syncthreads();

            if (t == 0 && g + 2 < 32) {
                int gn = g + 2;
                mbar_expect(mb0 + (gn & 1) * 8, 32768);
                bulk_g2s(smb + W2_OFF + (gn & 1) * 32768,
                         (const char*)g_w2t + (gn & 7) * 32768, 32768, mb0 + (gn & 1) * 8);
            }
        }

        // ---- epilogue: relu(acc2+b2) . W3, reduce, mask, sigmoid ----
        float s[2][2] = {{0.f, 0.f}, {0.f, 0.f}};
        #pragma unroll
        for (int mt = 0; mt < 2; mt++)
            #pragma unroll
            for (int nt = 0; nt < 8; nt++) {
                int k = wc * 64 + nt * 8 + lc;
                s[mt][0] += fmaxf(acc2[mt][nt][0] + b2s[k],     0.f) * w3s[k]
                          + fmaxf(acc2[mt][nt][1] + b2s[k + 1], 0.f) * w3s[k + 1];
                s[mt][1] += fmaxf(acc2[mt][nt][2] + b2s[k],     0.f) * w3s[k]
                          + fmaxf(acc2[mt][nt][3] + b2s[k + 1], 0.f) * w3s[k + 1];
            }
        #pragma unroll
        for (int off = 1; off <= 2; off <<= 1) {
            #pragma unroll
            for (int mt = 0; mt < 2; mt++) {
                s[mt][0] += __shfl_xor_sync(0xffffffffu, s[mt][0], off);
                s[mt][1] += __shfl_xor_sync(0xffffffffu, s[mt][1], off);
            }
        }
        if ((lane & 3) == 0) {
            #pragma unroll
            for (int mt = 0; mt < 2; mt++) {
                int r0 = wr * 32 + mt * 16 + lr;
                atomicAdd(&part[r0],     s[mt][0]);
                atomicAdd(&part[r0 + 8], s[mt][1]);
            }
        }
        __syncthreads();
        if (t < 64) {
            int j = jt * 64 + t;
            float lg = (part[t] + b3v) * mi * mmS[j];
            size_t o = (size_t)bi * Nn + j;
            out[o] = 1.f / (1.f + __expf(-lg));
            out[(size_t)Bb * Nn * Nn + o] = lg;
        }
        __syncthreads();
    }
}

extern "C" void kernel_launch(void* const* d_in, const int* in_sizes, int n_in,
                              void* d_out, int out_size)
{
    const float* z   = (const float*)d_in[0];
    const float* mmk = (const float*)d_in[1];
    const float* W1  = (const float*)d_in[3];
    const float* b1  = (const float*)d_in[4];
    const float* W2  = (const float*)d_in[5];
    const float* b2  = (const float*)d_in[6];
    const float* W3  = (const float*)d_in[7];
    const float* b3  = (const float*)d_in[8];
    float* out = (float*)d_out;

    cudaFuncSetAttribute(decoder_hmma_kernel,
                         cudaFuncAttributeMaxDynamicSharedMemorySize, MAIN_SMEM);

    prep_w2t_kernel<<<512, 256>>>(W2);
    prep_tmp_kernel<<<dim3(16, 16), 256>>>(z, W1);
    decoder_hmma_kernel<<<Bb * Nn, 256, MAIN_SMEM>>>(z, mmk, b1, b2, W3, b3, out);
}

// round 6
// speedup vs baseline: 24.5162x; 2.3144x over previous
#include <cuda_runtime.h>
#include <cuda_fp16.h>
#include <stdint.h>

#define Bb 4
#define Nn 256
#define Dd 32
#define Hh 512
#define Kk 256

// device scratch
__device__ uint4 g_tmph[((size_t)Bb*Nn*Hh*Dd*2)/16];   // 33.5 MB fp16 TMP [bi][h 512][c 32]
__device__ uint4 g_w2t [(8*Kk*128)/16];                 // 256 KB fp16 W2^T chunks, XOR-swizzled
__device__ int   g_jlist[Bb*Nn];
__device__ int   g_jcnt[Bb];

// ---------------- helpers ----------------
__device__ __forceinline__ uint32_t s2u(const void* p) {
    uint32_t a;
    asm("{ .reg .u64 t; cvta.to.shared.u64 t, %1; cvt.u32.u64 %0, t; }" : "=r"(a) : "l"(p));
    return a;
}
__device__ __forceinline__ void mbar_init(uint32_t m, uint32_t c) {
    asm volatile("mbarrier.init.shared.b64 [%0], %1;" :: "r"(m), "r"(c) : "memory");
}
__device__ __forceinline__ void mbar_expect(uint32_t m, uint32_t bytes) {
    asm volatile("mbarrier.arrive.expect_tx.shared.b64 _, [%0], %1;" :: "r"(m), "r"(bytes) : "memory");
}
__device__ __forceinline__ void mbar_wait(uint32_t m, uint32_t ph) {
    asm volatile(
        "{\n\t.reg .pred P;\n\t"
        "LW%=:\n\t"
        "mbarrier.try_wait.parity.shared.b64 P, [%0], %1, 0x989680;\n\t"
        "@P bra LD%=;\n\t"
        "bra LW%=;\n\t"
        "LD%=:\n\t}"
        :: "r"(m), "r"(ph) : "memory");
}
__device__ __forceinline__ void bulk_g2s(uint32_t dst, const void* src, uint32_t bytes, uint32_t mbar) {
    asm volatile("cp.async.bulk.shared::cluster.global.mbarrier::complete_tx::bytes [%0], [%1], %2, [%3];"
                 :: "r"(dst), "l"(src), "r"(bytes), "r"(mbar) : "memory");
}
__device__ __forceinline__ void mma16816(float d[4], const uint32_t a[4], uint32_t b0, uint32_t b1) {
    asm volatile("mma.sync.aligned.m16n8k16.row.col.f32.f16.f16.f32 "
                 "{%0,%1,%2,%3}, {%4,%5,%6,%7}, {%8,%9}, {%0,%1,%2,%3};"
                 : "+f"(d[0]), "+f"(d[1]), "+f"(d[2]), "+f"(d[3])
                 : "r"(a[0]), "r"(a[1]), "r"(a[2]), "r"(a[3]), "r"(b0), "r"(b1));
}
__device__ __forceinline__ void ldsm4(uint32_t r[4], uint32_t addr) {
    asm volatile("ldmatrix.sync.aligned.m8n8.x4.shared.b16 {%0,%1,%2,%3}, [%4];"
                 : "=r"(r[0]), "=r"(r[1]), "=r"(r[2]), "=r"(r[3]) : "r"(addr));
}

// ---------------- prep kernels ----------------
// active-j compaction lists, ordered (deterministic)
__global__ void __launch_bounds__(256) prep_mask_kernel(const float* __restrict__ mm) {
    __shared__ int wcnt[8], woff[8];
    int b = blockIdx.x, t = threadIdx.x, w = t >> 5, lane = t & 31;
    int act = (mm[b * Nn + t] != 0.f);
    unsigned bal = __ballot_sync(0xffffffffu, act);
    if (lane == 0) wcnt[w] = __popc(bal);
    __syncthreads();
    if (t == 0) { int s = 0; for (int q = 0; q < 8; q++) { woff[q] = s; s += wcnt[q]; } g_jcnt[b] = s; }
    __syncthreads();
    if (act) {
        int pos = woff[w] + __popc(bal & ((1u << lane) - 1u));
        g_jlist[b * Nn + pos] = t;
    }
}

// W2T chunk layout: [hc][k row 128B][64 h halves], bytes XOR-swizzled by ((k&7)<<4).
// FIXED: full coverage — 8 hc * 256 k * 32 half2 = 65536 threads (256 blocks).
__global__ void __launch_bounds__(256) prep_w2t_kernel(const float* __restrict__ W2) {
    int idx = blockIdx.x * 256 + threadIdx.x;
    int hc  = idx >> 13;            // 0..7
    int rem = idx & 8191;
    int k   = rem >> 5;             // 0..255
    int hcol = (rem & 31) * 2;      // 0,2,..,62
    __half2 v = __floats2half2_rn(W2[(hc * 64 + hcol) * Kk + k], W2[(hc * 64 + hcol + 1) * Kk + k]);
    uint32_t byt = (uint32_t)hc * 32768u + (uint32_t)k * 128u
                 + (((uint32_t)hcol * 2u) ^ (((uint32_t)k & 7u) << 4));
    *(__half2*)((char*)g_w2t + byt) = v;
}

// TMP[bi][h][c] = sum_a z[bi][a] * W1[(a*32+c)*512 + h]; staged + coalesced stores; skip inactive bi.
#define PT_ZS   0
#define PT_W1S  8448
#define PT_STG  41728
#define PT_SMEM 82688
__global__ void __launch_bounds__(256) prep_tmp_kernel(const float* __restrict__ z,
                                                       const float* __restrict__ W1,
                                                       const float* __restrict__ mm) {
    extern __shared__ char psm[];
    float* zs  = (float*)(psm + PT_ZS);     // [64][33]
    float* W1s = (float*)(psm + PT_W1S);    // [32][260]
    char*  stg = psm + PT_STG;              // [16 bi][32 h][40 halves pitch]
    __shared__ int actS[16];

    int it = blockIdx.x, ht = blockIdx.y, t = threadIdx.x;
    int c8 = t >> 5, hl = t & 31;

    for (int idx = t; idx < 64 * 32; idx += 256) {
        int r = idx >> 5, a = idx & 31;
        zs[r * 33 + a] = z[(it * 64 + r) * Dd + a];
    }
    __syncthreads();

    for (int ig = 0; ig < 4; ig++) {
        if (t < 16) actS[t] = (mm[it * 64 + ig * 16 + t] != 0.f);
        for (int fc = 0; fc < 4; fc++) {
            __syncthreads();
            {
                int c = fc * 8 + c8, h = ht * 32 + hl;
                #pragma unroll
                for (int a = 0; a < 32; a++)
                    W1s[a * 260 + t] = W1[(a * Dd + c) * Hh + h];
            }
            __syncthreads();
            float acc[16];
            #pragma unroll
            for (int ii = 0; ii < 16; ii++) acc[ii] = 0.f;
            #pragma unroll 8
            for (int a = 0; a < 32; a++) {
                float w = W1s[a * 260 + t];
                #pragma unroll
                for (int ii = 0; ii < 16; ii++)
                    acc[ii] += w * zs[(ig * 16 + ii) * 33 + a];
            }
            int c = fc * 8 + c8;
            #pragma unroll
            for (int ii = 0; ii < 16; ii++)
                *(__half*)(stg + ii * 2560 + hl * 80 + c * 2) = __float2half(acc[ii]);
        }
        __syncthreads();
        #pragma unroll
        for (int q = 0; q < 8; q++) {
            int idx = t + 256 * q;
            int bi_l = idx >> 7, rem = idx & 127, h_l = rem >> 2, qt = rem & 3;
            if (actS[bi_l]) {
                uint4 v = *(const uint4*)(stg + bi_l * 2560 + h_l * 80 + qt * 16);
                size_t bi = (size_t)it * 64 + ig * 16 + bi_l;
                *(uint4*)((char*)g_tmph + bi * 32768 + (ht * 32 + h_l) * 64 + qt * 16) = v;
            }
        }
        __syncthreads();
    }
}

// ---------------- main kernel ----------------
#define ZJ_OFF  0
#define TMP_OFF 20480
#define W2_OFF  61440
#define H1_OFF  126976
#define MAIN_SMEM 145408

__global__ void __launch_bounds__(256, 1)
decoder_hmma_kernel(const float* __restrict__ z, const float* __restrict__ mm,
                    const float* __restrict__ b1, const float* __restrict__ b2,
                    const float* __restrict__ W3, const float* __restrict__ b3,
                    float* __restrict__ out)
{
    extern __shared__ char dsm[];
    __shared__ float b1s[512], b2s[256], w3s[256], mmS[256], part[64];
    __shared__ int jlS[256];
    __shared__ __align__(8) uint64_t mbars[2];

    const int t    = threadIdx.x;
    const int w    = t >> 5;
    const int lane = t & 31;
    const int wr   = w >> 2;
    const int wc   = w & 3;
    const int lr   = lane >> 2;
    const int lc   = (lane & 3) * 2;
    const int mrow = lane & 7;
    const int mg   = lane >> 3;

    const int bi = blockIdx.x;
    const int b  = bi >> 8;
    const int i  = bi & 255;

    const uint32_t smb = s2u(dsm);
    const uint32_t mb0 = s2u(mbars);

    for (int k = t; k < 512; k += 256) b1s[k] = b1[k];
    b2s[t] = b2[t];
    w3s[t] = W3[t]; mmS[t] = mm[b * Nn + t]; jlS[t] = g_jlist[b * Nn + t];
    __syncthreads();

    const float mi = mmS[i];
    if (mi == 0.f || mmS[t] == 0.f) {
        size_t o = (size_t)bi * Nn + t;
        out[o] = 0.5f;
        out[(size_t)Bb * Nn * Nn + o] = 0.f;
    }
    if (mi == 0.f) return;

    const int Kact   = g_jcnt[b];
    const int ntiles = (Kact + 63) >> 6;
    const int totalg = ntiles * 8;

    if (t < ntiles * 64) {
        __half2* zr = (__half2*)(dsm + ZJ_OFF + t * 80);
        if (t < Kact) {
            const float4* zp = (const float4*)(z + ((size_t)b * Nn + jlS[t]) * Dd);
            #pragma unroll
            for (int c4 = 0; c4 < 8; c4++) {
                float4 v = zp[c4];
                zr[c4 * 2]     = __floats2half2_rn(v.x, v.y);
                zr[c4 * 2 + 1] = __floats2half2_rn(v.z, v.w);
            }
        } else {
            #pragma unroll
            for (int q = 0; q < 16; q++) zr[q] = __floats2half2_rn(0.f, 0.f);
        }
    }
    {
        const char* gsrc = (const char*)g_tmph + (size_t)bi * 32768;
        #pragma unroll
        for (int r8 = 0; r8 < 8; r8++) {
            int idx = t + 256 * r8;
            int row = idx >> 2, q = idx & 3;
            uint4 v = *(const uint4*)(gsrc + row * 64 + q * 16);
            *(uint4*)(dsm + TMP_OFF + row * 80 + q * 16) = v;
        }
    }
    if (t == 0) { mbar_init(mb0, 1); mbar_init(mb0 + 8, 1); }
    __syncthreads();
    if (t == 0) {
        mbar_expect(mb0, 32768);
        bulk_g2s(smb + W2_OFF, (const char*)g_w2t, 32768, mb0);
        if (totalg > 1) {
            mbar_expect(mb0 + 8, 32768);
            bulk_g2s(smb + W2_OFF + 32768, (const char*)g_w2t + 32768, 32768, mb0 + 8);
        }
    }

    const float b3v = b3[0];

    for (int jt = 0; jt < ntiles; jt++) {
        if (t < 64) part[t] = 0.f;
        float acc2[2][8][4];
        #pragma unroll
        for (int mt = 0; mt < 2; mt++)
            #pragma unroll
            for (int nt = 0; nt < 8; nt++)
                #pragma unroll
                for (int e = 0; e < 4; e++) acc2[mt][nt][e] = 0.f;

        for (int hc = 0; hc < 8; hc++) {
            const int g = jt * 8 + hc;

            // ---- MMA1: h1[64j x 64h] ----
            float acc1[2][2][4];
            #pragma unroll
            for (int mt = 0; mt < 2; mt++)
                #pragma unroll
                for (int nt = 0; nt < 2; nt++)
                    #pragma unroll
                    for (int e = 0; e < 4; e++) acc1[mt][nt][e] = 0.f;

            #pragma unroll
            for (int kk = 0; kk < 2; kk++) {
                uint32_t bf[4];
                {
                    int nh = hc * 64 + wc * 16 + (mg & 1) * 8 + mrow;
                    int cc = kk * 16 + (mg >> 1) * 8;
                    ldsm4(bf, smb + TMP_OFF + (uint32_t)(nh * 40 + cc) * 2);
                }
                #pragma unroll
                for (int mt = 0; mt < 2; mt++) {
                    uint32_t af[4];
                    int jr = jt * 64 + wr * 32 + mt * 16 + (mg & 1) * 8 + mrow;
                    int cc = kk * 16 + (mg >> 1) * 8;
                    ldsm4(af, smb + ZJ_OFF + (uint32_t)(jr * 40 + cc) * 2);
                    mma16816(acc1[mt][0], af, bf[0], bf[2]);
                    mma16816(acc1[mt][1], af, bf[1], bf[3]);
                }
            }
            char* h1p = dsm + H1_OFF + (g & 1) * 9216;
            #pragma unroll
            for (int mt = 0; mt < 2; mt++)
                #pragma unroll
                for (int nt = 0; nt < 2; nt++) {
                    int rl = wr * 32 + mt * 16 + lr;
                    int hl = wc * 16 + nt * 8 + lc;
                    int hg = hc * 64 + hl;
                    float v0 = fmaxf(acc1[mt][nt][0] + b1s[hg],     0.f);
                    float v1 = fmaxf(acc1[mt][nt][1] + b1s[hg + 1], 0.f);
                    float v2 = fmaxf(acc1[mt][nt][2] + b1s[hg],     0.f);
                    float v3 = fmaxf(acc1[mt][nt][3] + b1s[hg + 1], 0.f);
                    *(__half2*)(h1p + (rl * 72 + hl) * 2)       = __floats2half2_rn(v0, v1);
                    *(__half2*)(h1p + ((rl + 8) * 72 + hl) * 2) = __floats2half2_rn(v2, v3);
                }

            mbar_wait(mb0 + (g & 1) * 8, (g >> 1) & 1);
            __syncthreads();

            if (t == 0 && g >= 1 && g + 1 < totalg) {
                int gn = g + 1;
                mbar_expect(mb0 + (gn & 1) * 8, 32768);
                bulk_g2s(smb + W2_OFF + (gn & 1) * 32768,
                         (const char*)g_w2t + (gn & 7) * 32768, 32768, mb0 + (gn & 1) * 8);
            }

            // ---- MMA2: acc2 += h1 @ W2chunk (K=64) ----
            const uint32_t wb = smb + W2_OFF + (g & 1) * 32768u;
            #pragma unroll
            for (int kk = 0; kk < 4; kk++) {
                uint32_t bfs[4][4];
                #pragma unroll
                for (int p = 0; p < 4; p++) {
                    int n  = wc * 64 + p * 16 + (mg & 1) * 8 + mrow;
                    uint32_t kb = (uint32_t)((kk * 16 + (mg >> 1) * 8) * 2);
                    uint32_t byt = kb ^ (((uint32_t)n & 7u) << 4);
                    ldsm4(bfs[p], wb + (uint32_t)n * 128u + byt);
                }
                #pragma unroll
                for (int mt = 0; mt < 2; mt++) {
                    uint32_t af[4];
                    int rl = wr * 32 + mt * 16 + (mg & 1) * 8 + mrow;
                    int cc = kk * 16 + (mg >> 1) * 8;
                    ldsm4(af, s2u(h1p) + (uint32_t)(rl * 72 + cc) * 2);
                    #pragma unroll
                    for (int p = 0; p < 4; p++) {
                        mma16816(acc2[mt][2 * p],     af, bfs[p][0], bfs[p][2]);
                        mma16816(acc2[mt][2 * p + 1], af, bfs[p][1], bfs[p][3]);
                    }
                }
            }
        }

        // ---- epilogue ----
        float s[2][2] = {{0.f, 0.f}, {0.f, 0.f}};
        #pragma unroll
        for (int mt = 0; mt < 2; mt++)
            #pragma unroll
            for (int nt = 0; nt < 8; nt++) {
                int k = wc * 64 + nt * 8 + lc;
                s[mt][0] += fmaxf(acc2[mt][nt][0] + b2s[k],     0.f) * w3s[k]
                          + fmaxf(acc2[mt][nt][1] + b2s[k + 1], 0.f) * w3s[k + 1];
                s[mt][1] += fmaxf(acc2[mt][nt][2] + b2s[k],     0.f) * w3s[k]
                          + fmaxf(acc2[mt][nt][3] + b2s[k + 1], 0.f) * w3s[k + 1];
            }
        #pragma unroll
        for (int off = 1; off <= 2; off <<= 1) {
            #pragma unroll
            for (int mt = 0; mt < 2; mt++) {
                s[mt][0] += __shfl_xor_sync(0xffffffffu, s[mt][0], off);
                s[mt][1] += __shfl_xor_sync(0xffffffffu, s[mt][1], off);
            }
        }
        __syncthreads();
        if ((lane & 3) == 0) {
            #pragma unroll
            for (int mt = 0; mt < 2; mt++) {
                int r0 = wr * 32 + mt * 16 + lr;
                atomicAdd(&part[r0],     s[mt][0]);
                atomicAdd(&part[r0 + 8], s[mt][1]);
            }
        }
        __syncthreads();
        if (t < 64) {
            int idx = jt * 64 + t;
            if (idx < Kact) {
                int j = jlS[idx];
                float lg = part[t] + b3v;
                size_t o = (size_t)bi * Nn + j;
                out[o] = 1.f / (1.f + __expf(-lg));
                out[(size_t)Bb * Nn * Nn + o] = lg;
            }
        }
        __syncthreads();
    }
}

extern "C" void kernel_launch(void* const* d_in, const int* in_sizes, int n_in,
                              void* d_out, int out_size)
{
    const float* z   = (const float*)d_in[0];
    const float* mmk = (const float*)d_in[1];
    const float* W1  = (const float*)d_in[3];
    const float* b1  = (const float*)d_in[4];
    const float* W2  = (const float*)d_in[5];
    const float* b2  = (const float*)d_in[6];
    const float* W3  = (const float*)d_in[7];
    const float* b3  = (const float*)d_in[8];
    float* out = (float*)d_out;

    cudaFuncSetAttribute(decoder_hmma_kernel,
                         cudaFuncAttributeMaxDynamicSharedMemorySize, MAIN_SMEM);
    cudaFuncSetAttribute(prep_tmp_kernel,
                         cudaFuncAttributeMaxDynamicSharedMemorySize, PT_SMEM);

    prep_mask_kernel<<<Bb, 256>>>(mmk);
    prep_w2t_kernel<<<256, 256>>>(W2);
    prep_tmp_kernel<<<dim3(16, 16), 256, PT_SMEM>>>(z, W1, mmk);
    decoder_hmma_kernel<<<Bb * Nn, 256, MAIN_SMEM>>>(z, mmk, b1, b2, W3, b3, out);
}